// round 1
// baseline (speedup 1.0000x reference)
#include <cuda_runtime.h>
#include <cstdint>

#define NB 8
#define NA 49104
#define NC 90
#define IMGF 512.0f
#define SCORE_THR 0.2f
#define IOU_THR 0.2f
#define K_PRE 1000
#define K_OUT 100

// ---------------- scratch (no allocations allowed) ----------------
__device__ float g_maxs[NB * NA];
__device__ int   g_cls [NB * NA];
__device__ unsigned long long g_top[NB * K_PRE];

// ---------------- K1: per-anchor max score + argmax class ----------------
__global__ void k_maxarg(const float* __restrict__ cls) {
    int t = blockIdx.x * blockDim.x + threadIdx.x;
    if (t >= NB * NA) return;
    const float2* row = reinterpret_cast<const float2*>(cls + (size_t)t * NC);
    float best = -1e30f;
    int bi = 0;
#pragma unroll
    for (int i = 0; i < NC / 2; i++) {
        float2 v = row[i];
        if (v.x > best) { best = v.x; bi = 2 * i; }
        if (v.y > best) { best = v.y; bi = 2 * i + 1; }
    }
    g_maxs[t] = best;
    g_cls[t]  = bi;
}

// ---------------- K2: per-image exact top-K_PRE selection ----------------
// key64 = (scorebits << 32) | (0xFFFFFFFF - index): descending sort gives
// score desc, index asc on ties — exactly lax.top_k ordering.
__global__ void k_select() {
    const int b = blockIdx.x;
    const float* sc = g_maxs + (size_t)b * NA;
    const int tid = threadIdx.x;
    const int NT = 1024;

    __shared__ int hist[256];
    __shared__ int s_valid;
    __shared__ unsigned s_prefix;
    __shared__ int s_krem;
    __shared__ int s_cnt;
    __shared__ unsigned long long buf[2048];

    if (tid == 0) s_valid = 0;
    __syncthreads();

    // count valid (score > thr)
    int lv = 0;
    for (int i = tid; i < NA; i += NT) if (sc[i] > SCORE_THR) lv++;
    atomicAdd(&s_valid, lv);
    __syncthreads();

    const int K = min(K_PRE, s_valid);

    unsigned prefix = 0;
    int krem = K;
    if (K > 0) {
        for (int level = 0; level < 4; level++) {
            int shift = 24 - 8 * level;
            if (tid < 256) hist[tid] = 0;
            __syncthreads();
            for (int i = tid; i < NA; i += NT) {
                float s = sc[i];
                unsigned key = (s > SCORE_THR) ? __float_as_uint(s) : 0u;
                bool match = (level == 0) || ((key >> (shift + 8)) == (prefix >> (shift + 8)));
                if (match) atomicAdd(&hist[(key >> shift) & 0xFF], 1);
            }
            __syncthreads();
            if (tid == 0) {
                int cum = 0, bsel = 0;
                for (int x = 255; x >= 0; x--) {
                    if (cum + hist[x] >= krem) { bsel = x; break; }
                    cum += hist[x];
                }
                s_prefix = prefix | ((unsigned)bsel << shift);
                s_krem = krem - cum;
            }
            __syncthreads();
            prefix = s_prefix;
            krem = s_krem;
            __syncthreads();
        }
    }
    const unsigned T = prefix;  // exact K-th largest key (T > 0 since K <= valid)

    if (tid == 0) s_cnt = 0;
    __syncthreads();

    if (K > 0) {
        for (int i = tid; i < NA; i += NT) {
            float s = sc[i];
            unsigned key = (s > SCORE_THR) ? __float_as_uint(s) : 0u;
            if (key >= T && key > 0u) {
                int p = atomicAdd(&s_cnt, 1);
                if (p < 2048)
                    buf[p] = ((unsigned long long)key << 32) |
                             (unsigned long long)(0xFFFFFFFFu - (unsigned)i);
            }
        }
    }
    __syncthreads();
    int n = min(s_cnt, 2048);
    for (int i = n + tid; i < 2048; i += NT) buf[i] = 0ULL;
    __syncthreads();

    // bitonic sort, descending, n=2048
    for (int k = 2; k <= 2048; k <<= 1) {
        for (int j = k >> 1; j > 0; j >>= 1) {
            for (int i = tid; i < 2048; i += NT) {
                int ixj = i ^ j;
                if (ixj > i) {
                    bool descBlock = ((i & k) == 0);
                    unsigned long long a = buf[i], c = buf[ixj];
                    bool swap = descBlock ? (a < c) : (a > c);
                    if (swap) { buf[i] = c; buf[ixj] = a; }
                }
            }
            __syncthreads();
        }
    }

    for (int i = tid; i < K_PRE; i += NT)
        g_top[(size_t)b * K_PRE + i] = (i < K) ? buf[i] : 0ULL;
}

// ---------------- K3: decode top candidates + greedy NMS + output ----------------
__global__ void k_nms(const float* __restrict__ loc,
                      const float* __restrict__ anchors,
                      float* __restrict__ out) {
    const int b = blockIdx.x;
    const int tid = threadIdx.x;  // 256 threads

    __shared__ float4 sbox[K_PRE];
    __shared__ float  sval[K_PRE];
    __shared__ int    scls[K_PRE];
    __shared__ int    kept[K_OUT];
    __shared__ int    s_nkept;

    for (int i = tid; i < K_PRE; i += 256) {
        unsigned long long key = g_top[(size_t)b * K_PRE + i];
        if (key == 0ULL) {
            sval[i] = -1.0f; scls[i] = -1;
            sbox[i] = make_float4(0.f, 0.f, 0.f, 0.f);
            continue;
        }
        unsigned idx = 0xFFFFFFFFu - (unsigned)(key & 0xFFFFFFFFull);
        float score = __uint_as_float((unsigned)(key >> 32));
        float ay1 = anchors[idx * 4 + 0], ax1 = anchors[idx * 4 + 1];
        float ay2 = anchors[idx * 4 + 2], ax2 = anchors[idx * 4 + 3];
        float ya = (ay1 + ay2) * 0.5f, xa = (ax1 + ax2) * 0.5f;
        float ha = ay2 - ay1, wa = ax2 - ax1;
        const float* lp = loc + ((size_t)b * NA + idx) * 4;
        float dy = lp[0], dx = lp[1], dh = lp[2], dw = lp[3];
        float h = expf(dh) * ha;
        float w = expf(dw) * wa;
        float yc = dy * ha + ya;
        float xc = dx * wa + xa;
        float x1 = fminf(fmaxf(xc - 0.5f * w, 0.f), IMGF);
        float y1 = fminf(fmaxf(yc - 0.5f * h, 0.f), IMGF);
        float x2 = fminf(fmaxf(xc + 0.5f * w, 0.f), IMGF);
        float y2 = fminf(fmaxf(yc + 0.5f * h, 0.f), IMGF);
        sbox[i] = make_float4(x1, y1, x2, y2);
        sval[i] = score;
        scls[i] = g_cls[(size_t)b * NA + idx];
    }
    if (tid == 0) s_nkept = 0;
    __syncthreads();

    // warp 0: greedy NMS (candidates already score-descending)
    if (tid < 32) {
        int nk = 0;
        for (int i = 0; i < K_PRE && nk < K_OUT; i++) {
            float v = sval[i];                 // uniform broadcast
            if (!(v > SCORE_THR)) continue;
            float4 bi = sbox[i];
            int ci = scls[i];
            float areai = (bi.z - bi.x) * (bi.w - bi.y);
            bool sup = false;
            for (int j = tid; j < nk; j += 32) {
                int kj = kept[j];
                if (scls[kj] != ci) continue;  // class offset trick => cross-class IoU = 0
                float4 bj = sbox[kj];
                float xx1 = fmaxf(bi.x, bj.x), yy1 = fmaxf(bi.y, bj.y);
                float xx2 = fminf(bi.z, bj.z), yy2 = fminf(bi.w, bj.w);
                float inter = fmaxf(xx2 - xx1, 0.f) * fmaxf(yy2 - yy1, 0.f);
                float areaj = (bj.z - bj.x) * (bj.w - bj.y);
                float iou = inter / (areai + areaj - inter + 1e-8f);
                if (iou > IOU_THR) sup = true;
            }
            unsigned any = __ballot_sync(0xFFFFFFFFu, sup);
            if (any == 0u) {
                if (tid == 0) kept[nk] = i;
                __syncwarp();
                nk++;
            }
        }
        if (tid == 0) s_nkept = nk;
    }
    __syncthreads();
    const int nk = s_nkept;

    // output: boxes [B,100,4] | scores [B,100] | labels [B,100], all float32
    float* oboxes  = out + (size_t)b * K_OUT * 4;
    float* oscores = out + (size_t)NB * K_OUT * 4 + (size_t)b * K_OUT;
    float* olabels = out + (size_t)NB * K_OUT * 5 + (size_t)b * K_OUT;
    for (int s = tid; s < K_OUT; s += 256) {
        if (s < nk) {
            int i = kept[s];
            float4 bb = sbox[i];
            oboxes[s * 4 + 0] = bb.x;
            oboxes[s * 4 + 1] = bb.y;
            oboxes[s * 4 + 2] = bb.z;
            oboxes[s * 4 + 3] = bb.w;
            oscores[s] = sval[i];
            olabels[s] = (float)scls[i];
        } else {
            oboxes[s * 4 + 0] = 0.f;
            oboxes[s * 4 + 1] = 0.f;
            oboxes[s * 4 + 2] = 1.f;
            oboxes[s * 4 + 3] = 1.f;
            oscores[s] = 0.f;
            olabels[s] = -1.f;
        }
    }
}

// ---------------- launch ----------------
extern "C" void kernel_launch(void* const* d_in, const int* in_sizes, int n_in,
                              void* d_out, int out_size) {
    const float* cls     = (const float*)d_in[0];
    const float* loc     = (const float*)d_in[1];
    const float* anchors = (const float*)d_in[2];
    float* out = (float*)d_out;

    k_maxarg<<<(NB * NA + 255) / 256, 256>>>(cls);
    k_select<<<NB, 1024>>>();
    k_nms<<<NB, 256>>>(loc, anchors, out);
}